// round 14
// baseline (speedup 1.0000x reference)
#include <cuda_runtime.h>
#include <cuda_fp16.h>
#include <mma.h>
#include <cstdint>

using namespace nvcuda;

// Problem constants (fixed: B=8,S=2048,D=1024,E=8,F=4096)
#define T_TOK 16384
#define DIM   1024
#define NE    8
#define FF    4096

typedef __half fp16;

// ---------------- scratch (device globals: allocation-free rule) ----------
__device__ int  g_off[NE + 1];
__device__ int  g_cursor[NE];
__device__ int  g_perm[T_TOK];
__device__ int  g_expidx[T_TOK];
__device__ fp16 g_xh[(size_t)T_TOK * DIM];        // x in fp16
__device__ fp16 g_w1h[(size_t)NE * DIM * FF];     // w1 in fp16
__device__ fp16 g_w2h[(size_t)NE * DIM * FF];     // w2 in fp16
__device__ fp16 g_Hh[(size_t)T_TOK * FF];         // hidden in fp16

// ---------------- helpers ---------------------------------------------------
__device__ __forceinline__ void cpasync16(uint32_t dst, const void* src) {
    asm volatile("cp.async.cg.shared.global [%0], [%1], 16;\n"
                 :: "r"(dst), "l"(src));
}
__device__ __forceinline__ void cpasync_commit() {
    asm volatile("cp.async.commit_group;\n" ::: "memory");
}
template <int N>
__device__ __forceinline__ void cpasync_wait() {
    asm volatile("cp.async.wait_group %0;\n" :: "n"(N) : "memory");
}
__device__ __forceinline__ uint32_t smem_u32(const void* p) {
    uint32_t a;
    asm("{ .reg .u64 t; cvta.to.shared.u64 t, %1; cvt.u32.u64 %0, t; }"
        : "=r"(a) : "l"(p));
    return a;
}

// ---------------- small kernels -------------------------------------------
// One warp per token: logits + argmax (first max); also writes x as fp16.
__global__ void router_kernel(const float* __restrict__ x,
                              const float* __restrict__ rw,
                              const float* __restrict__ rb,
                              uint2* __restrict__ xh) {
    int warp = (blockIdx.x * blockDim.x + threadIdx.x) >> 5;
    int lane = threadIdx.x & 31;
    if (warp >= T_TOK) return;
    const float* xr = x + (size_t)warp * DIM;
    float acc[NE];
#pragma unroll
    for (int e = 0; e < NE; e++) acc[e] = 0.f;
    for (int d = lane; d < DIM; d += 32) {
        float xv = xr[d];
        const float4* w4 = (const float4*)(rw + d * NE);
        float4 a = w4[0], b = w4[1];
        acc[0] += xv * a.x; acc[1] += xv * a.y; acc[2] += xv * a.z; acc[3] += xv * a.w;
        acc[4] += xv * b.x; acc[5] += xv * b.y; acc[6] += xv * b.z; acc[7] += xv * b.w;
    }
#pragma unroll
    for (int o = 16; o > 0; o >>= 1)
#pragma unroll
        for (int e = 0; e < NE; e++) acc[e] += __shfl_down_sync(0xffffffffu, acc[e], o);
    if (lane == 0) {
        int bi = 0;
        float bv = acc[0] + rb[0];
#pragma unroll
        for (int e = 1; e < NE; e++) {
            float v = acc[e] + rb[e];
            if (v > bv) { bv = v; bi = e; }   // strict > == first max (jnp.argmax)
        }
        g_expidx[warp] = bi;
    }
    // x -> fp16 (row is hot in L1)
    const float4* x4 = (const float4*)xr;
    uint2* xo = xh + (size_t)warp * (DIM / 4);
#pragma unroll
    for (int i = 0; i < DIM / 128; i++) {
        int c = lane + 32 * i;
        float4 v = x4[c];
        __half2 h01 = __floats2half2_rn(v.x, v.y);
        __half2 h23 = __floats2half2_rn(v.z, v.w);
        uint2 hw;
        hw.x = *(uint32_t*)&h01; hw.y = *(uint32_t*)&h23;
        xo[c] = hw;
    }
}

// Single block: count experts, offsets, cursors, lb_loss.
__global__ void setup_kernel(float* out_loss, int write_loss) {
    __shared__ int sc[NE];
    const int tid = threadIdx.x;   // 256
    if (tid < NE) sc[tid] = 0;
    __syncthreads();
    int cnt[NE];
#pragma unroll
    for (int e = 0; e < NE; e++) cnt[e] = 0;
    for (int t = tid; t < T_TOK; t += 256) {
        int ei = g_expidx[t];
#pragma unroll
        for (int e = 0; e < NE; e++) cnt[e] += (ei == e);
    }
#pragma unroll
    for (int e = 0; e < NE; e++)
        if (cnt[e]) atomicAdd(&sc[e], cnt[e]);
    __syncthreads();
    if (tid == 0) {
        int off = 0;
        for (int e = 0; e < NE; e++) { g_off[e] = off; g_cursor[e] = off; off += sc[e]; }
        g_off[NE] = off;
        if (write_loss) {
            float lb = 0.f;
            for (int e = 0; e < NE; e++) {
                float u = (float)sc[e] / (float)T_TOK - 1.0f / NE;
                lb += u * u;
            }
            *out_loss = lb / NE;
        }
    }
}

// z=0: scatter tokens to g_perm (first 64 blocks). z=1/2: w1/w2 -> fp16.
__global__ void scatter_wconvert_kernel(const float4* __restrict__ w1,
                                        const float4* __restrict__ w2,
                                        uint2* __restrict__ w1h,
                                        uint2* __restrict__ w2h) {
    const int z = blockIdx.z;
    if (z == 0) {
        int t = blockIdx.x * blockDim.x + threadIdx.x;
        if (t >= T_TOK) return;
        int e = g_expidx[t];
        int p = atomicAdd(&g_cursor[e], 1);
        g_perm[p] = t;
        return;
    }
    const float4* src = (z == 1) ? w1 : w2;
    uint2* dh = (z == 1) ? w1h : w2h;
    const long n4 = (long)NE * DIM * FF / 4;
    long i = (long)blockIdx.x * blockDim.x + threadIdx.x;
    const long stride = (long)gridDim.x * blockDim.x;
    for (; i < n4; i += stride) {
        float4 v = src[i];
        __half2 h01 = __floats2half2_rn(v.x, v.y);
        __half2 h23 = __floats2half2_rn(v.z, v.w);
        uint2 hw;
        hw.x = *(uint32_t*)&h01; hw.y = *(uint32_t*)&h23;
        dh[i] = hw;
    }
}

// ---------------- grouped GEMM: pure fp16, fp32 accumulate ------------------
// C = act( A @ W + bias ),  A,W fp16, accum fp32.
// CTA BMv x 256 x 32, 256 threads = 8 warps ((BMv/WTM) M x (256/WTN) N).
// 3-stage cp.async pipeline (prefetch distance 2, one sync per k-tile).
// GEMM1: BMv=128, WTM=64 (exact round-9 config, 46.5% tensor, proven).
// GEMM2: BMv=64,  WTM=32 -> 1024 CTAs = 6.9 waves -> ~1% tail (was 15%).
constexpr int BN = 256, BK = 32;
constexpr int THREADS = 256;
constexpr int ALD = 40;                    // fp16 per A smem row (80 B)
constexpr int BLD = 264;                   // fp16 per B smem row (528 B)
constexpr int B_T = BK * BLD * 2;          // 16896 B

typedef wmma::fragment<wmma::matrix_a, 16, 16, 16, fp16, wmma::row_major> FragA;
typedef wmma::fragment<wmma::matrix_b, 16, 16, 16, fp16, wmma::row_major> FragB;
typedef wmma::fragment<wmma::accumulator, 16, 16, 16, float> FragC;

template <int BMv, int WTM, bool GATHER_A, bool SCATTER_C, bool RELU, bool HALF_OUT>
__global__ __launch_bounds__(THREADS, 1)
void moe_gemm_f1(const fp16* __restrict__ A, const fp16* __restrict__ W,
                 const float* __restrict__ bias, float* __restrict__ C,
                 fp16* __restrict__ Ch, int K, int N) {
    constexpr int A_T   = BMv * ALD * 2;
    constexpr int STAGE = A_T + B_T;
    constexpr int NI    = WTM / 16;           // A frags per warp
    constexpr int ARPT  = BMv / 64;           // A rows staged per thread (1|2)
    constexpr int WTN   = 64;                 // 4 warps over N
    constexpr int NJ    = WTN / 16;

    extern __shared__ __align__(16) char smem[];
    const uint32_t base = smem_u32(smem);

    const int tid  = threadIdx.x;
    const int warp = tid >> 5;
    const int lane = tid & 31;
    const int wm = warp >> 2;    // (BMv/WTM) warps over M
    const int wn = warp & 3;     // 4 warps over N (64 cols)

    const int e    = blockIdx.z;
    const int m0   = g_off[e];
    const int rows = g_off[e + 1] - m0;
    const int n0   = blockIdx.x * BN;
    const fp16* We = W + (size_t)e * K * N;
    const float* be = bias + (size_t)e * N;
    const int ktiles = K / BK;

    // cp.async per-thread slots (256 threads)
    const int a_r = tid >> 2;          // A rows a_r (+64 if ARPT==2)
    const int a_c = tid & 3;           // 16B chunk (8 fp16) in BK=32
    const int b_r = tid >> 5;          // B rows b_r, +8, +16, +24
    const int b_c = tid & 31;          // 16B chunk in BN=256
    const uint32_t aoff = (uint32_t)a_r * 80u + a_c * 16u;

    for (int tm = blockIdx.y; tm * BMv < rows; tm += gridDim.y) {
        const int rowt = tm * BMv;

        const fp16* aph[ARPT];
#pragma unroll
        for (int q = 0; q < ARPT; q++) {
            int p = m0 + min(rowt + a_r + 64 * q, rows - 1);
            aph[q] = A + (GATHER_A ? (size_t)g_perm[p] * K : (size_t)p * K);
        }

        FragC fc[NI][NJ];
#pragma unroll
        for (int i = 0; i < NI; i++)
#pragma unroll
            for (int j = 0; j < NJ; j++) wmma::fill_fragment(fc[i][j], 0.f);

        // prefetch k-tiles 0,1
#pragma unroll
        for (int pk = 0; pk < 2; pk++) {
            uint32_t sb = base + pk * STAGE;
            int kb = pk * BK;
#pragma unroll
            for (int q = 0; q < ARPT; q++)
                cpasync16(sb + aoff + q * (64u * 80u), aph[q] + kb + a_c * 8);
#pragma unroll
            for (int q = 0; q < 4; q++) {
                uint32_t boff = (uint32_t)(b_r + 8 * q) * 528u + b_c * 16u;
                cpasync16(sb + A_T + boff,
                          We + (size_t)(kb + b_r + 8 * q) * N + n0 + b_c * 8);
            }
            cpasync_commit();
        }

        for (int kt = 0; kt < ktiles; kt++) {
            if (kt < ktiles - 1) cpasync_wait<1>();
            else                 cpasync_wait<0>();
            __syncthreads();

            // prefetch kt+2 into stage (kt+2)%3
            const int nk = kt + 2;
            if (nk < ktiles) {
                const int s = nk - (nk / 3) * 3;
                uint32_t sb = base + s * STAGE;
                int kb = nk * BK;
#pragma unroll
                for (int q = 0; q < ARPT; q++)
                    cpasync16(sb + aoff + q * (64u * 80u), aph[q] + kb + a_c * 8);
#pragma unroll
                for (int q = 0; q < 4; q++) {
                    uint32_t boff = (uint32_t)(b_r + 8 * q) * 528u + b_c * 16u;
                    cpasync16(sb + A_T + boff,
                              We + (size_t)(kb + b_r + 8 * q) * N + n0 + b_c * 8);
                }
                cpasync_commit();
            }

            const int cur = kt - (kt / 3) * 3;
            const fp16* As = (const fp16*)(smem + cur * STAGE);
            const fp16* Bs = (const fp16*)(smem + cur * STAGE + A_T);

#pragma unroll
            for (int kk = 0; kk < BK / 16; kk++) {
                FragB fb[NJ];
#pragma unroll
                for (int j = 0; j < NJ; j++)
                    wmma::load_matrix_sync(fb[j],
                        Bs + kk * 16 * BLD + wn * WTN + j * 16, BLD);
#pragma unroll
                for (int i = 0; i < NI; i++) {
                    FragA fa;
                    wmma::load_matrix_sync(fa,
                        As + (wm * WTM + i * 16) * ALD + kk * 16, ALD);
#pragma unroll
                    for (int j = 0; j < NJ; j++)
                        wmma::mma_sync(fc[i][j], fa, fb[j], fc[i][j]);
                }
            }
        }

        __syncthreads();   // done with pipeline smem; reuse for staging

        // epilogue: per-warp 16x16 staging (fp32), bias(+relu), store
        float* stage = (float*)(smem) + warp * (16 * 20);
#pragma unroll
        for (int i = 0; i < NI; i++)
#pragma unroll
            for (int j = 0; j < NJ; j++) {
                wmma::store_matrix_sync(stage, fc[i][j], 20, wmma::mem_row_major);
                __syncwarp();
#pragma unroll
                for (int t = 0; t < 2; t++) {
                    int idx = lane + 32 * t;        // 64 slots: 16 rows x 4 f4
                    int rr = idx >> 2, cc4 = idx & 3;
                    int r = wm * WTM + i * 16 + rr;
                    int c = n0 + wn * WTN + j * 16 + cc4 * 4;
                    if (rowt + r < rows) {
                        float4 v = *(float4*)&stage[rr * 20 + cc4 * 4];
                        float4 b = *(const float4*)&be[c];
                        v.x += b.x; v.y += b.y; v.z += b.z; v.w += b.w;
                        if (RELU) {
                            v.x = fmaxf(v.x, 0.f); v.y = fmaxf(v.y, 0.f);
                            v.z = fmaxf(v.z, 0.f); v.w = fmaxf(v.w, 0.f);
                        }
                        if (HALF_OUT) {
                            size_t orow = (size_t)(m0 + rowt + r);
                            __half2 p0 = __floats2half2_rn(v.x, v.y);
                            __half2 p1 = __floats2half2_rn(v.z, v.w);
                            uint2 hw;
                            hw.x = *(uint32_t*)&p0; hw.y = *(uint32_t*)&p1;
                            *(uint2*)&Ch[orow * (size_t)N + c] = hw;
                        } else {
                            size_t orow = SCATTER_C ? (size_t)g_perm[m0 + rowt + r]
                                                    : (size_t)(m0 + rowt + r);
                            *(float4*)&C[orow * (size_t)N + c] = v;
                        }
                    }
                }
                __syncwarp();
            }
        __syncthreads();   // staging aliases stage 0; next tm prefetch writes it
    }
}

// ---------------- launch ----------------------------------------------------
extern "C" void kernel_launch(void* const* d_in, const int* in_sizes, int n_in,
                              void* d_out, int out_size) {
    const float* x  = (const float*)d_in[0];
    const float* rw = (const float*)d_in[1];
    const float* rb = (const float*)d_in[2];
    const float* w1 = (const float*)d_in[3];
    const float* b1 = (const float*)d_in[4];
    const float* w2 = (const float*)d_in[5];
    const float* b2 = (const float*)d_in[6];
    float* out = (float*)d_out;

    void* p;
    cudaGetSymbolAddress(&p, g_xh);  fp16* xh  = (fp16*)p;
    cudaGetSymbolAddress(&p, g_w1h); fp16* w1h = (fp16*)p;
    cudaGetSymbolAddress(&p, g_w2h); fp16* w2h = (fp16*)p;
    cudaGetSymbolAddress(&p, g_Hh);  fp16* Hh  = (fp16*)p;

    constexpr int SMEM1 = 3 * (128 * ALD * 2 + B_T) + 256;   // ~81.6 KB
    constexpr int SMEM2 = 3 * (64  * ALD * 2 + B_T) + 256;   // ~66.3 KB
    cudaFuncSetAttribute(moe_gemm_f1<128, 64, true,  false, true,  true>,
                         cudaFuncAttributeMaxDynamicSharedMemorySize, SMEM1);
    cudaFuncSetAttribute(moe_gemm_f1<64,  32, false, true,  false, false>,
                         cudaFuncAttributeMaxDynamicSharedMemorySize, SMEM2);

    const long long main_elems = (long long)T_TOK * DIM;
    int write_loss = ((long long)out_size > main_elems) ? 1 : 0;

    // 5 launches; ncu captures the 4th -> GEMM1.
    router_kernel<<<T_TOK / 8, 256>>>(x, rw, rb, (uint2*)xh);              // 1
    setup_kernel<<<1, 256>>>(out + (size_t)T_TOK * DIM, write_loss);       // 2
    scatter_wconvert_kernel<<<dim3(1024, 1, 3), 256>>>(                    // 3
        (const float4*)w1, (const float4*)w2, (uint2*)w1h, (uint2*)w2h);

    // GEMM1: Hh = fp16(relu(x[perm,:] @ w1[e] + b1[e]))   K=DIM, N=FF
    moe_gemm_f1<128, 64, true, false, true, true>                          // 4
        <<<dim3(FF / BN, 16, NE), THREADS, SMEM1>>>(
            xh, w1h, b1, nullptr, Hh, DIM, FF);
    // GEMM2: out[perm,:] = Hh @ w2[e] + b2[e]             K=FF, N=DIM
    moe_gemm_f1<64, 32, false, true, false, false>                         // 5
        <<<dim3(DIM / BN, 32, NE), THREADS, SMEM2>>>(
            Hh, w2h, b2, out, nullptr, FF, DIM);
}

// round 15
// speedup vs baseline: 1.1115x; 1.1115x over previous
#include <cuda_runtime.h>
#include <cuda_fp16.h>
#include <mma.h>
#include <cstdint>

using namespace nvcuda;

// Problem constants (fixed: B=8,S=2048,D=1024,E=8,F=4096)
#define T_TOK 16384
#define DIM   1024
#define NE    8
#define FF    4096

typedef __half fp16;

// ---------------- scratch (device globals: allocation-free rule) ----------
__device__ int   g_off[NE + 1];
__device__ int   g_cursor[NE];
__device__ int   g_perm[T_TOK];
__device__ int   g_expidx[T_TOK];
__device__ fp16  g_xh[(size_t)T_TOK * DIM];       // x in fp16
__device__ fp16  g_w1h[(size_t)NE * DIM * FF];    // w1 in fp16
__device__ fp16  g_w2h[(size_t)NE * DIM * FF];    // w2 in fp16
__device__ fp16  g_Hh[(size_t)T_TOK * FF];        // hidden in fp16
__device__ float g_P0[(size_t)T_TOK * DIM];       // GEMM2 split-K partial 0
__device__ float g_P1[(size_t)T_TOK * DIM];       // GEMM2 split-K partial 1

// ---------------- helpers ---------------------------------------------------
__device__ __forceinline__ void cpasync16(uint32_t dst, const void* src) {
    asm volatile("cp.async.cg.shared.global [%0], [%1], 16;\n"
                 :: "r"(dst), "l"(src));
}
__device__ __forceinline__ void cpasync_commit() {
    asm volatile("cp.async.commit_group;\n" ::: "memory");
}
template <int N>
__device__ __forceinline__ void cpasync_wait() {
    asm volatile("cp.async.wait_group %0;\n" :: "n"(N) : "memory");
}
__device__ __forceinline__ uint32_t smem_u32(const void* p) {
    uint32_t a;
    asm("{ .reg .u64 t; cvta.to.shared.u64 t, %1; cvt.u32.u64 %0, t; }"
        : "=r"(a) : "l"(p));
    return a;
}

// ---------------- small kernels -------------------------------------------
// z=0: router (warp/token) + x->fp16.  z=1/2: w1/w2 -> fp16 (grid-stride).
__global__ void router_convert_kernel(const float* __restrict__ x,
                                      const float* __restrict__ rw,
                                      const float* __restrict__ rb,
                                      uint2* __restrict__ xh,
                                      const float4* __restrict__ w1,
                                      const float4* __restrict__ w2,
                                      uint2* __restrict__ w1h,
                                      uint2* __restrict__ w2h) {
    const int z = blockIdx.z;
    if (z != 0) {
        const float4* src = (z == 1) ? w1 : w2;
        uint2* dh = (z == 1) ? w1h : w2h;
        const long n4 = (long)NE * DIM * FF / 4;
        long i = (long)blockIdx.x * blockDim.x + threadIdx.x;
        const long stride = (long)gridDim.x * blockDim.x;
        for (; i < n4; i += stride) {
            float4 v = src[i];
            __half2 h01 = __floats2half2_rn(v.x, v.y);
            __half2 h23 = __floats2half2_rn(v.z, v.w);
            uint2 hw;
            hw.x = *(uint32_t*)&h01; hw.y = *(uint32_t*)&h23;
            dh[i] = hw;
        }
        return;
    }
    int warp = (blockIdx.x * blockDim.x + threadIdx.x) >> 5;
    int lane = threadIdx.x & 31;
    if (warp >= T_TOK) return;
    const float* xr = x + (size_t)warp * DIM;
    float acc[NE];
#pragma unroll
    for (int e = 0; e < NE; e++) acc[e] = 0.f;
    for (int d = lane; d < DIM; d += 32) {
        float xv = xr[d];
        const float4* w4 = (const float4*)(rw + d * NE);
        float4 a = w4[0], b = w4[1];
        acc[0] += xv * a.x; acc[1] += xv * a.y; acc[2] += xv * a.z; acc[3] += xv * a.w;
        acc[4] += xv * b.x; acc[5] += xv * b.y; acc[6] += xv * b.z; acc[7] += xv * b.w;
    }
#pragma unroll
    for (int o = 16; o > 0; o >>= 1)
#pragma unroll
        for (int e = 0; e < NE; e++) acc[e] += __shfl_down_sync(0xffffffffu, acc[e], o);
    if (lane == 0) {
        int bi = 0;
        float bv = acc[0] + rb[0];
#pragma unroll
        for (int e = 1; e < NE; e++) {
            float v = acc[e] + rb[e];
            if (v > bv) { bv = v; bi = e; }   // strict > == first max (jnp.argmax)
        }
        g_expidx[warp] = bi;
    }
    // x -> fp16 (row is hot in L1)
    const float4* x4 = (const float4*)xr;
    uint2* xo = xh + (size_t)warp * (DIM / 4);
#pragma unroll
    for (int i = 0; i < DIM / 128; i++) {
        int c = lane + 32 * i;
        float4 v = x4[c];
        __half2 h01 = __floats2half2_rn(v.x, v.y);
        __half2 h23 = __floats2half2_rn(v.z, v.w);
        uint2 hw;
        hw.x = *(uint32_t*)&h01; hw.y = *(uint32_t*)&h23;
        xo[c] = hw;
    }
}

// Single block: count experts, offsets, cursors, lb_loss.
__global__ void setup_kernel(float* out_loss, int write_loss) {
    __shared__ int sc[NE];
    const int tid = threadIdx.x;   // 256
    if (tid < NE) sc[tid] = 0;
    __syncthreads();
    int cnt[NE];
#pragma unroll
    for (int e = 0; e < NE; e++) cnt[e] = 0;
    for (int t = tid; t < T_TOK; t += 256) {
        int ei = g_expidx[t];
#pragma unroll
        for (int e = 0; e < NE; e++) cnt[e] += (ei == e);
    }
#pragma unroll
    for (int e = 0; e < NE; e++)
        if (cnt[e]) atomicAdd(&sc[e], cnt[e]);
    __syncthreads();
    if (tid == 0) {
        int off = 0;
        for (int e = 0; e < NE; e++) { g_off[e] = off; g_cursor[e] = off; off += sc[e]; }
        g_off[NE] = off;
        if (write_loss) {
            float lb = 0.f;
            for (int e = 0; e < NE; e++) {
                float u = (float)sc[e] / (float)T_TOK - 1.0f / NE;
                lb += u * u;
            }
            *out_loss = lb / NE;
        }
    }
}

__global__ void scatter_kernel() {
    int t = blockIdx.x * blockDim.x + threadIdx.x;
    if (t >= T_TOK) return;
    int e = g_expidx[t];
    int p = atomicAdd(&g_cursor[e], 1);
    g_perm[p] = t;
}

// out[perm[p],:] = P0[p,:] + P1[p,:] + b2[e(p)]
__global__ void reduce_out_kernel(const float4* __restrict__ P0,
                                  const float4* __restrict__ P1,
                                  const float* __restrict__ b2,
                                  float4* __restrict__ out) {
    int idx = blockIdx.x * blockDim.x + threadIdx.x;   // T*D/4 = 4M
    int p  = idx >> 8;           // D/4 = 256 float4 per row
    int c4 = idx & 255;
    int e = 0;
#pragma unroll
    for (int q = 0; q < NE - 1; q++) e += (p >= g_off[q + 1]);
    float4 a = P0[idx], b = P1[idx];
    float4 bb = ((const float4*)(b2 + (size_t)e * DIM))[c4];
    float4 v;
    v.x = a.x + b.x + bb.x; v.y = a.y + b.y + bb.y;
    v.z = a.z + b.z + bb.z; v.w = a.w + b.w + bb.w;
    out[(size_t)g_perm[p] * 256 + c4] = v;
}

// ---------------- grouped GEMM: pure fp16, fp32 accumulate ------------------
// C = act( A @ W + bias ),  A,W fp16, accum fp32.
// CTA 128x256x32, 256 threads = 8 warps (2M x 4N), warp tile 64x64.
// 3-stage cp.async pipeline. EXACT round-9/13 mainloop (proven 46.5% tensor).
// SPLITK: kz = blockIdx.y&1 selects K half; writes fp32 partials (no bias).
constexpr int BM = 128, BN = 256, BK = 32;
constexpr int THREADS = 256;
constexpr int ALD = 40;                    // fp16 per A smem row (80 B)
constexpr int BLD = 264;                   // fp16 per B smem row (528 B)
constexpr int A_T = BM * ALD * 2;          // 10240 B
constexpr int B_T = BK * BLD * 2;          // 16896 B
constexpr int STAGE = A_T + B_T;           // 27136 B
constexpr int SMEM_BYTES = 3 * STAGE + 256;   // ~81.6 KB

typedef wmma::fragment<wmma::matrix_a, 16, 16, 16, fp16, wmma::row_major> FragA;
typedef wmma::fragment<wmma::matrix_b, 16, 16, 16, fp16, wmma::row_major> FragB;
typedef wmma::fragment<wmma::accumulator, 16, 16, 16, float> FragC;

template <bool GATHER_A, bool RELU, bool HALF_OUT, bool SPLITK>
__global__ __launch_bounds__(THREADS, 1)
void moe_gemm_f1(const fp16* __restrict__ A, const fp16* __restrict__ W,
                 const float* __restrict__ bias, float* __restrict__ C0,
                 float* __restrict__ C1, fp16* __restrict__ Ch,
                 int K, int N) {
    extern __shared__ __align__(16) char smem[];
    const uint32_t base = smem_u32(smem);

    const int tid  = threadIdx.x;
    const int warp = tid >> 5;
    const int lane = tid & 31;
    const int wm = warp >> 2;    // 2 warps over M (64 rows)
    const int wn = warp & 3;     // 4 warps over N (64 cols)

    const int e    = blockIdx.z;
    const int m0   = g_off[e];
    const int rows = g_off[e + 1] - m0;
    const int n0   = blockIdx.x * BN;

    // split-K decode
    const int kz     = SPLITK ? (blockIdx.y & 1) : 0;
    const int tmb    = SPLITK ? (blockIdx.y >> 1) : blockIdx.y;
    const int tms    = SPLITK ? (gridDim.y >> 1) : gridDim.y;
    const int Klen   = SPLITK ? (K >> 1) : K;
    const int k0     = kz * Klen;
    float* Cp        = (SPLITK && kz) ? C1 : C0;

    const fp16* We = W + (size_t)e * K * N + (size_t)k0 * N;
    const float* be = bias;   // per-expert bias row (nullptr-safe when SPLITK)
    const int ktiles = Klen / BK;

    // cp.async per-thread slots (256 threads)
    const int a_r = tid >> 2;          // A rows a_r, a_r+64
    const int a_c = tid & 3;           // 16B chunk (8 fp16) in BK=32
    const int b_r = tid >> 5;          // B rows b_r, +8, +16, +24
    const int b_c = tid & 31;          // 16B chunk in BN=256
    const uint32_t aoff = (uint32_t)a_r * 80u + a_c * 16u;

    for (int tm = tmb; tm * BM < rows; tm += tms) {
        const int rowt = tm * BM;

        const fp16* aph[2];
#pragma unroll
        for (int q = 0; q < 2; q++) {
            int p = m0 + min(rowt + a_r + 64 * q, rows - 1);
            aph[q] = A + (GATHER_A ? (size_t)g_perm[p] * K : (size_t)p * K) + k0;
        }

        FragC fc[4][4];
#pragma unroll
        for (int i = 0; i < 4; i++)
#pragma unroll
            for (int j = 0; j < 4; j++) wmma::fill_fragment(fc[i][j], 0.f);

        // prefetch k-tiles 0,1
#pragma unroll
        for (int pk = 0; pk < 2; pk++) {
            uint32_t sb = base + pk * STAGE;
            int kb = pk * BK;
            cpasync16(sb + aoff,              aph[0] + kb + a_c * 8);
            cpasync16(sb + aoff + 64u * 80u,  aph[1] + kb + a_c * 8);
#pragma unroll
            for (int q = 0; q < 4; q++) {
                uint32_t boff = (uint32_t)(b_r + 8 * q) * 528u + b_c * 16u;
                cpasync16(sb + A_T + boff,
                          We + (size_t)(kb + b_r + 8 * q) * N + n0 + b_c * 8);
            }
            cpasync_commit();
        }

        for (int kt = 0; kt < ktiles; kt++) {
            if (kt < ktiles - 1) cpasync_wait<1>();
            else                 cpasync_wait<0>();
            __syncthreads();

            const int nk = kt + 2;
            if (nk < ktiles) {
                const int s = nk - (nk / 3) * 3;
                uint32_t sb = base + s * STAGE;
                int kb = nk * BK;
                cpasync16(sb + aoff,              aph[0] + kb + a_c * 8);
                cpasync16(sb + aoff + 64u * 80u,  aph[1] + kb + a_c * 8);
#pragma unroll
                for (int q = 0; q < 4; q++) {
                    uint32_t boff = (uint32_t)(b_r + 8 * q) * 528u + b_c * 16u;
                    cpasync16(sb + A_T + boff,
                              We + (size_t)(kb + b_r + 8 * q) * N + n0 + b_c * 8);
                }
                cpasync_commit();
            }

            const int cur = kt - (kt / 3) * 3;
            const fp16* As = (const fp16*)(smem + cur * STAGE);
            const fp16* Bs = (const fp16*)(smem + cur * STAGE + A_T);

#pragma unroll
            for (int kk = 0; kk < BK / 16; kk++) {
                FragB fb[4];
#pragma unroll
                for (int j = 0; j < 4; j++)
                    wmma::load_matrix_sync(fb[j],
                        Bs + kk * 16 * BLD + wn * 64 + j * 16, BLD);
#pragma unroll
                for (int i = 0; i < 4; i++) {
                    FragA fa;
                    wmma::load_matrix_sync(fa,
                        As + (wm * 64 + i * 16) * ALD + kk * 16, ALD);
#pragma unroll
                    for (int j = 0; j < 4; j++)
                        wmma::mma_sync(fc[i][j], fa, fb[j], fc[i][j]);
                }
            }
        }

        __syncthreads();   // done with pipeline smem; reuse for staging

        // epilogue: per-warp 16x16 staging (fp32)
        float* stage = (float*)(smem) + warp * (16 * 20);
#pragma unroll
        for (int i = 0; i < 4; i++)
#pragma unroll
            for (int j = 0; j < 4; j++) {
                wmma::store_matrix_sync(stage, fc[i][j], 20, wmma::mem_row_major);
                __syncwarp();
#pragma unroll
                for (int t = 0; t < 2; t++) {
                    int idx = lane + 32 * t;        // 64 slots: 16 rows x 4 f4
                    int rr = idx >> 2, cc4 = idx & 3;
                    int r = wm * 64 + i * 16 + rr;
                    int c = n0 + wn * 64 + j * 16 + cc4 * 4;
                    if (rowt + r < rows) {
                        float4 v = *(float4*)&stage[rr * 20 + cc4 * 4];
                        if (!SPLITK) {
                            float4 b = *(const float4*)&be[(size_t)e * N + c];
                            v.x += b.x; v.y += b.y; v.z += b.z; v.w += b.w;
                        }
                        if (RELU) {
                            v.x = fmaxf(v.x, 0.f); v.y = fmaxf(v.y, 0.f);
                            v.z = fmaxf(v.z, 0.f); v.w = fmaxf(v.w, 0.f);
                        }
                        size_t orow = (size_t)(m0 + rowt + r);
                        if (HALF_OUT) {
                            __half2 p0 = __floats2half2_rn(v.x, v.y);
                            __half2 p1 = __floats2half2_rn(v.z, v.w);
                            uint2 hw;
                            hw.x = *(uint32_t*)&p0; hw.y = *(uint32_t*)&p1;
                            *(uint2*)&Ch[orow * (size_t)N + c] = hw;
                        } else {
                            *(float4*)&Cp[orow * (size_t)N + c] = v;
                        }
                    }
                }
                __syncwarp();
            }
        __syncthreads();   // staging aliases stage 0; next tm prefetch writes it
    }
}

// ---------------- launch ----------------------------------------------------
extern "C" void kernel_launch(void* const* d_in, const int* in_sizes, int n_in,
                              void* d_out, int out_size) {
    const float* x  = (const float*)d_in[0];
    const float* rw = (const float*)d_in[1];
    const float* rb = (const float*)d_in[2];
    const float* w1 = (const float*)d_in[3];
    const float* b1 = (const float*)d_in[4];
    const float* w2 = (const float*)d_in[5];
    const float* b2 = (const float*)d_in[6];
    float* out = (float*)d_out;

    void* p;
    cudaGetSymbolAddress(&p, g_xh);  fp16* xh  = (fp16*)p;
    cudaGetSymbolAddress(&p, g_w1h); fp16* w1h = (fp16*)p;
    cudaGetSymbolAddress(&p, g_w2h); fp16* w2h = (fp16*)p;
    cudaGetSymbolAddress(&p, g_Hh);  fp16* Hh  = (fp16*)p;
    cudaGetSymbolAddress(&p, g_P0);  float* P0 = (float*)p;
    cudaGetSymbolAddress(&p, g_P1);  float* P1 = (float*)p;

    cudaFuncSetAttribute(moe_gemm_f1<true,  true,  true,  false>,
                         cudaFuncAttributeMaxDynamicSharedMemorySize, SMEM_BYTES);
    cudaFuncSetAttribute(moe_gemm_f1<false, false, false, true>,
                         cudaFuncAttributeMaxDynamicSharedMemorySize, SMEM_BYTES);

    const long long main_elems = (long long)T_TOK * DIM;
    int write_loss = ((long long)out_size > main_elems) ? 1 : 0;

    // 6 launches; ncu captures the 4th -> GEMM1.
    router_convert_kernel<<<dim3(T_TOK / 8, 1, 3), 256>>>(                 // 1
        x, rw, rb, (uint2*)xh, (const float4*)w1, (const float4*)w2,
        (uint2*)w1h, (uint2*)w2h);
    setup_kernel<<<1, 256>>>(out + (size_t)T_TOK * DIM, write_loss);       // 2
    scatter_kernel<<<T_TOK / 256, 256>>>();                                // 3

    // GEMM1: Hh = fp16(relu(x[perm,:] @ w1[e] + b1[e]))   K=DIM, N=FF
    moe_gemm_f1<true, true, true, false>                                   // 4
        <<<dim3(FF / BN, 16, NE), THREADS, SMEM_BYTES>>>(
            xh, w1h, b1, nullptr, nullptr, Hh, DIM, FF);
    // GEMM2 split-K=2: P(kz)[p,:] = Hh[p, kz*2048:...] @ w2half   (fp32)
    moe_gemm_f1<false, false, false, true>                                 // 5
        <<<dim3(DIM / BN, 32, NE), THREADS, SMEM_BYTES>>>(
            Hh, w2h, nullptr, P0, P1, nullptr, FF, DIM);
    // reduce: out[perm[p],:] = P0 + P1 + b2[e]
    reduce_out_kernel<<<(T_TOK * DIM / 4) / 256, 256>>>(                   // 6
        (const float4*)P0, (const float4*)P1, b2, (float4*)out);
}